// round 1
// baseline (speedup 1.0000x reference)
#include <cuda_runtime.h>
#include <cstdint>

// Problem constants (fixed by setup_inputs)
#define BATCH   8
#define HH      128
#define WW      128
#define CC      256
#define HID     64
#define NTOK    (HH*WW)          // 16384 tokens per batch
#define NP      1024             // 32x32 patches per batch
#define KKEEP   768
#define NPW     32               // patches per row
#define TOK_ALL (BATCH*NTOK)     // 131072

// Scratch (device globals — no allocation allowed)
__device__ float g_imp[TOK_ALL];
__device__ int   g_idx[BATCH*KKEEP];

// ---------------- packed f32x2 helpers ----------------
static __device__ __forceinline__ unsigned long long ffma2(
    unsigned long long a, unsigned long long b, unsigned long long c) {
    unsigned long long d;
    asm("fma.rn.f32x2 %0, %1, %2, %3;" : "=l"(d) : "l"(a), "l"(b), "l"(c));
    return d;
}
static __device__ __forceinline__ unsigned long long dup2(float x) {
    unsigned long long r;
    unsigned int u = __float_as_uint(x);
    asm("mov.b64 %0, {%1, %1};" : "=l"(r) : "r"(u));
    return r;
}
static __device__ __forceinline__ float2 unpack2(unsigned long long v) {
    unsigned int lo, hi;
    asm("mov.b64 {%0, %1}, %2;" : "=r"(lo), "=r"(hi) : "l"(v));
    float2 f; f.x = __uint_as_float(lo); f.y = __uint_as_float(hi);
    return f;
}

static __device__ __forceinline__ float gelu_exact(float v) {
    return 0.5f * v * (1.0f + erff(v * 0.7071067811865476f));
}

// ---------------- Kernel A: per-token importance (MLP) ----------------
// GEMM: [TOK_ALL, 256] x [256, 64] -> gelu -> dot w2 -> sigmoid -> g_imp
#define BM 128
#define BK 32
#define BN 64
#define AS_STRIDE (BM + 2)   // pad 2 keeps 8B alignment for paired-row LDS.64

__global__ __launch_bounds__(256) void score_kernel(
    const float* __restrict__ tokens,
    const float* __restrict__ w1,
    const float* __restrict__ b1,
    const float* __restrict__ w2,
    const float* __restrict__ b2)
{
    __shared__ __align__(16) float As[BK][AS_STRIDE];  // [k][m]
    __shared__ __align__(16) float Bs[BK][BN];         // [k][n]

    const int tid = threadIdx.x;
    const int tx  = tid & 15;     // col group (4 cols)
    const int ty  = tid >> 4;     // row group (8 rows = 4 row-pairs)
    const int m0  = blockIdx.x * BM;

    // 4 row-pairs x 4 cols of packed accumulators
    unsigned long long acc[4][4];
#pragma unroll
    for (int u = 0; u < 4; u++)
#pragma unroll
        for (int j = 0; j < 4; j++) acc[u][j] = 0ull;

    for (int kk = 0; kk < CC; kk += BK) {
        // A tile: 128 rows x 32 cols (float4 loads, scatter to k-major)
#pragma unroll
        for (int it = 0; it < 4; it++) {
            int r  = it * 32 + (tid >> 3);
            int c4 = tid & 7;
            float4 v = *(const float4*)(tokens + (size_t)(m0 + r) * CC + kk + c4 * 4);
            As[c4 * 4 + 0][r] = v.x;
            As[c4 * 4 + 1][r] = v.y;
            As[c4 * 4 + 2][r] = v.z;
            As[c4 * 4 + 3][r] = v.w;
        }
        // B tile: 32 rows x 64 cols
#pragma unroll
        for (int it = 0; it < 2; it++) {
            int r  = it * 16 + (tid >> 4);
            int c4 = tid & 15;
            *(float4*)&Bs[r][c4 * 4] =
                *(const float4*)(w1 + (size_t)(kk + r) * HID + c4 * 4);
        }
        __syncthreads();

#pragma unroll
        for (int k = 0; k < BK; k++) {
            unsigned long long a2[4];
#pragma unroll
            for (int u = 0; u < 4; u++)
                a2[u] = *(const unsigned long long*)&As[k][ty * 8 + u * 2];
            float4 bv = *(const float4*)&Bs[k][tx * 4];
            unsigned long long bb[4];
            bb[0] = dup2(bv.x); bb[1] = dup2(bv.y);
            bb[2] = dup2(bv.z); bb[3] = dup2(bv.w);
#pragma unroll
            for (int u = 0; u < 4; u++)
#pragma unroll
                for (int j = 0; j < 4; j++)
                    acc[u][j] = ffma2(a2[u], bb[j], acc[u][j]);
        }
        __syncthreads();
    }

    // Epilogue: gelu(h + b1) * w2, partial over this thread's 4 cols
    float b1r[4], w2r[4];
#pragma unroll
    for (int j = 0; j < 4; j++) {
        b1r[j] = b1[tx * 4 + j];
        w2r[j] = w2[tx * 4 + j];
    }
    const float bias2 = b2[0];

    float part[8];
#pragma unroll
    for (int i = 0; i < 8; i++) part[i] = 0.0f;
#pragma unroll
    for (int u = 0; u < 4; u++)
#pragma unroll
        for (int j = 0; j < 4; j++) {
            float2 h = unpack2(acc[u][j]);
            part[2 * u + 0] += gelu_exact(h.x + b1r[j]) * w2r[j];
            part[2 * u + 1] += gelu_exact(h.y + b1r[j]) * w2r[j];
        }

    // Reduce across the 16 tx threads per row (reuse As memory)
    float (*red)[17] = (float(*)[17])&As[0][0];   // 128*17*4 = 8704B <= As size
    __syncthreads();
#pragma unroll
    for (int i = 0; i < 8; i++)
        red[ty * 8 + i][tx] = part[i];
    __syncthreads();

    if (tid < BM) {
        float s = 0.0f;
#pragma unroll
        for (int t = 0; t < 16; t++) s += red[tid][t];
        s += bias2;
        g_imp[m0 + tid] = 1.0f / (1.0f + expf(-s));
    }
}

// ---------------- Kernel B: patch scores + top-768 selection ----------------
__global__ __launch_bounds__(1024) void select_kernel()
{
    const int b = blockIdx.x;
    const int p = threadIdx.x;           // patch id 0..1023
    __shared__ float s[NP];
    __shared__ int   woff[32];

    const int pr = p >> 5, pc = p & 31;
    const float* base = g_imp + b * NTOK;
    float sum = 0.0f;
#pragma unroll
    for (int i = 0; i < 4; i++)
#pragma unroll
        for (int j = 0; j < 4; j++)
            sum += base[(pr * 4 + i) * WW + pc * 4 + j];
    s[p] = sum;                          // sum is monotone in mean; ranking identical
    __syncthreads();

    const float sp = sum;
    int rank = 0;
    for (int j = 0; j < NP; j++) {
        float v = s[j];
        rank += (int)((v > sp) || (v == sp && j < p));   // stable like lax.top_k
    }
    const bool kept = (rank < KKEEP);

    const unsigned mask = __ballot_sync(0xffffffffu, kept);
    const int lane = p & 31, warp = p >> 5;
    const int lpre = __popc(mask & ((1u << lane) - 1u));
    if (lane == 0) woff[warp] = __popc(mask);
    __syncthreads();
    if (p < 32) {
        int v = woff[p];
        int inc = v;
        for (int d = 1; d < 32; d <<= 1) {
            int t = __shfl_up_sync(0xffffffffu, inc, d);
            if (lane >= d) inc += t;
        }
        woff[p] = inc - v;               // exclusive prefix
    }
    __syncthreads();
    if (kept)
        g_idx[b * KKEEP + woff[warp] + lpre] = p;
}

// ---------------- Kernel C: gather + spatial reassembly ----------------
// Each kept patch = 4 contiguous segments of 1024 floats (4 adjacent tokens).
__global__ __launch_bounds__(128) void gather_kernel(
    const float* __restrict__ tokens, float* __restrict__ out)
{
    const int k = blockIdx.x;            // kept slot 0..767
    const int b = blockIdx.y;
    const int p = g_idx[b * KKEEP + k];
    const int pr = p >> 5, pc = p & 31;
    const int kr = k >> 5, kc = k & 31;

    const float4* src = (const float4*)(tokens + (size_t)b * NTOK * CC);
    float4*       dst = (float4*)(out + (size_t)b * (KKEEP * 16) * CC);
    const int t = threadIdx.x;

#pragma unroll
    for (int i = 0; i < 4; i++) {
        size_t so = (size_t)((pr * 4 + i) * WW + pc * 4) * (CC / 4);
        size_t dofs = (size_t)((kr * 4 + i) * WW + kc * 4) * (CC / 4);
#pragma unroll
        for (int it = 0; it < 2; it++) {
            int e = it * 128 + t;        // 256 float4 = 1024 floats per segment
            dst[dofs + e] = src[so + e];
        }
    }
}

// ---------------- launch ----------------
extern "C" void kernel_launch(void* const* d_in, const int* in_sizes, int n_in,
                              void* d_out, int out_size)
{
    const float* tokens = (const float*)d_in[0];
    const float* w1 = (const float*)d_in[1];
    const float* b1 = (const float*)d_in[2];
    const float* w2 = (const float*)d_in[3];
    const float* b2 = (const float*)d_in[4];
    (void)in_sizes; (void)n_in; (void)out_size;

    score_kernel<<<TOK_ALL / BM, 256>>>(tokens, w1, b1, w2, b2);
    select_kernel<<<BATCH, 1024>>>();
    gather_kernel<<<dim3(KKEEP, BATCH), 128>>>(tokens, (float*)d_out);
}

// round 3
// speedup vs baseline: 1.1337x; 1.1337x over previous
#include <cuda_runtime.h>
#include <cuda_fp16.h>
#include <cstdint>

// Problem constants (fixed by setup_inputs)
#define BATCH   8
#define HH      128
#define WW      128
#define CC      256
#define HID     64
#define NTOK    (HH*WW)          // 16384 tokens per batch
#define NP      1024
#define KKEEP   768
#define TOK_ALL (BATCH*NTOK)     // 131072
#define BM      256
#define NBLK    (TOK_ALL/BM)     // 512

// Scratch (device globals — no allocation allowed)
__device__ float g_imp[TOK_ALL];
__device__ int   g_idx[BATCH*KKEEP];

// ---------------- SMEM layout (bytes) ----------------
// B (w1) hi/lo in 8x8-tile-blocked fp16: 32KB + 32KB
// A chunk (256 rows x 32 k) hi/lo blocked: 16KB + 16KB
#define OFF_BH  0
#define OFF_BL  32768
#define OFF_AH  65536
#define OFF_AL  81920
#define OFF_B1  98304
#define OFF_W2  98560
#define SMEM_SZ 98816

// ---------------- asm helpers ----------------
static __device__ __forceinline__ uint32_t smem_u32(const void* p) {
    uint32_t a;
    asm("{ .reg .u64 t; cvta.to.shared.u64 t, %1; cvt.u32.u64 %0, t; }" : "=r"(a) : "l"(p));
    return a;
}
static __device__ __forceinline__ uint32_t h2u(__half2 h) {
    return *reinterpret_cast<uint32_t*>(&h);
}
#define LDSM_X4(r, a) \
    asm volatile("ldmatrix.sync.aligned.m8n8.x4.shared.b16 {%0,%1,%2,%3}, [%4];" \
        : "=r"((r)[0]), "=r"((r)[1]), "=r"((r)[2]), "=r"((r)[3]) : "r"(a))
#define LDSM_X2T(r, a) \
    asm volatile("ldmatrix.sync.aligned.m8n8.x2.trans.shared.b16 {%0,%1}, [%2];" \
        : "=r"((r)[0]), "=r"((r)[1]) : "r"(a))
#define MMA16816(d, a, b) \
    asm volatile("mma.sync.aligned.m16n8k16.row.col.f32.f16.f16.f32 " \
        "{%0,%1,%2,%3}, {%4,%5,%6,%7}, {%8,%9}, {%0,%1,%2,%3};" \
        : "+f"((d)[0]), "+f"((d)[1]), "+f"((d)[2]), "+f"((d)[3]) \
        : "r"((a)[0]), "r"((a)[1]), "r"((a)[2]), "r"((a)[3]), "r"((b)[0]), "r"((b)[1]))

static __device__ __forceinline__ float gelu_exact(float v) {
    return 0.5f * v * (1.0f + erff(v * 0.7071067811865476f));
}

// ============ Kernel A: fp16x2-split HMMA MLP -> per-token importance ============
// H = gelu(X[131072,256] @ W1[256,64] + b1); imp = sigmoid(H @ w2 + b2)
__global__ __launch_bounds__(256) void score_mma(
    const float* __restrict__ tokens,
    const float* __restrict__ w1,
    const float* __restrict__ b1,
    const float* __restrict__ w2,
    const float* __restrict__ b2)
{
    extern __shared__ char sm[];
    const uint32_t sb = smem_u32(sm);
    const int tid = threadIdx.x;
    const int lane = tid & 31, wid = tid >> 5;
    const int g = lane >> 2, tig = lane & 3;

    // ---- constants to smem ----
    if (tid < 64) {
        ((float*)(sm + OFF_B1))[tid] = b1[tid];
        ((float*)(sm + OFF_W2))[tid] = w2[tid];
    }
    const float b2v = b2[0];

    // ---- stage w1 hi/lo into 8x8-blocked fp16 tiles ----
    // elem (k,n) -> tile (k>>3)*8+(n>>3), byte (k&7)*16 + (n&7)*2
#pragma unroll
    for (int j = 0; j < 32; ++j) {
        int pi = tid + j * 256;            // 8192 half2 pairs
        int k = pi >> 5, n = (pi & 31) * 2;
        float2 v = *(const float2*)(w1 + k * HID + n);
        __half2 h = __floats2half2_rn(v.x, v.y);
        __half2 l = __floats2half2_rn(v.x - __low2float(h), v.y - __high2float(h));
        uint32_t off = (uint32_t)(((k >> 3) * 8 + (n >> 3)) * 128 + (k & 7) * 16 + (n & 7) * 2);
        *(uint32_t*)(sm + OFF_BH + off) = h2u(h);
        *(uint32_t*)(sm + OFF_BL + off) = h2u(l);
    }

    // ---- prefetch A chunk 0 ----
    // thread -> (rowgroup tid>>3 of 32, float4 col tid&7); 8 passes of 32 rows
    const float4* ap = (const float4*)(tokens + (size_t)(blockIdx.x * BM + (tid >> 3)) * CC)
                       + (tid & 7);
    float4 pf[8];
#pragma unroll
    for (int p = 0; p < 8; ++p) pf[p] = ap[p * 2048];   // 32 rows * 64 f4/row

    float acc[2][8][4];
#pragma unroll
    for (int mi = 0; mi < 2; ++mi)
#pragma unroll
        for (int nt = 0; nt < 8; ++nt)
#pragma unroll
            for (int q = 0; q < 4; ++q) acc[mi][nt][q] = 0.0f;

    const int rb = tid >> 3;
    const int k4 = (tid & 7) * 4;

    for (int c = 0; c < 8; ++c) {
        __syncthreads();                    // prior chunk's mma reads done
        // convert + store A chunk c (hi/lo split)
#pragma unroll
        for (int p = 0; p < 8; ++p) {
            const int r = p * 32 + rb;
            float4 v = pf[p];
            __half2 h0 = __floats2half2_rn(v.x, v.y);
            __half2 h1 = __floats2half2_rn(v.z, v.w);
            __half2 l0 = __floats2half2_rn(v.x - __low2float(h0), v.y - __high2float(h0));
            __half2 l1 = __floats2half2_rn(v.z - __low2float(h1), v.w - __high2float(h1));
            uint32_t off = (uint32_t)(((r >> 3) * 4 + (k4 >> 3)) * 128 + (r & 7) * 16 + (k4 & 7) * 2);
            *(uint2*)(sm + OFF_AH + off) = make_uint2(h2u(h0), h2u(h1));
            *(uint2*)(sm + OFF_AL + off) = make_uint2(h2u(l0), h2u(l1));
        }
        // prefetch next chunk (hidden behind the mma section)
        if (c < 7) {
#pragma unroll
            for (int p = 0; p < 8; ++p) pf[p] = ap[p * 2048 + (c + 1) * 8];
        }
        __syncthreads();

#pragma unroll
        for (int step = 0; step < 2; ++step) {
            uint32_t ah[2][4], al[2][4];
#pragma unroll
            for (int mi = 0; mi < 2; ++mi) {
                int r  = wid * 32 + mi * 16 + (lane & 15);
                int kt = step * 2 + (lane >> 4);
                uint32_t adr = sb + OFF_AH +
                    (uint32_t)(((r >> 3) * 4 + kt) * 128 + (r & 7) * 16);
                LDSM_X4(ah[mi], adr);
                LDSM_X4(al[mi], adr + 16384);
            }
            const int ktg = c * 4 + step * 2;
            const uint32_t brow = sb + OFF_BH +
                (uint32_t)(((ktg + ((lane >> 3) & 1)) * 8) * 128 + (lane & 7) * 16);
#pragma unroll
            for (int nt = 0; nt < 8; ++nt) {
                uint32_t bh[2], bl[2];
                uint32_t adr = brow + nt * 128;
                LDSM_X2T(bh, adr);
                LDSM_X2T(bl, adr + 32768);
#pragma unroll
                for (int mi = 0; mi < 2; ++mi) {
                    MMA16816(acc[mi][nt], ah[mi], bh);   // hi*hi
                    MMA16816(acc[mi][nt], ah[mi], bl);   // hi*lo
                    MMA16816(acc[mi][nt], al[mi], bh);   // lo*hi
                }
            }
        }
    }

    // ---- epilogue: gelu(h+b1)*w2, reduce 64 cols, sigmoid ----
    const float* b1s = (const float*)(sm + OFF_B1);
    const float* w2s = (const float*)(sm + OFF_W2);
#pragma unroll
    for (int mi = 0; mi < 2; ++mi) {
        float p0 = 0.0f, p1 = 0.0f;
#pragma unroll
        for (int nt = 0; nt < 8; ++nt) {
            int c0 = nt * 8 + tig * 2, c1 = c0 + 1;
            float bb0 = b1s[c0], bb1 = b1s[c1];
            float ww0 = w2s[c0], ww1 = w2s[c1];
            p0 += gelu_exact(acc[mi][nt][0] + bb0) * ww0
                + gelu_exact(acc[mi][nt][1] + bb1) * ww1;
            p1 += gelu_exact(acc[mi][nt][2] + bb0) * ww0
                + gelu_exact(acc[mi][nt][3] + bb1) * ww1;
        }
        p0 += __shfl_xor_sync(0xffffffffu, p0, 1);
        p0 += __shfl_xor_sync(0xffffffffu, p0, 2);
        p1 += __shfl_xor_sync(0xffffffffu, p1, 1);
        p1 += __shfl_xor_sync(0xffffffffu, p1, 2);
        if (tig == 0) {
            int r0 = blockIdx.x * BM + wid * 32 + mi * 16 + g;
            g_imp[r0]     = 1.0f / (1.0f + expf(-(p0 + b2v)));
            g_imp[r0 + 8] = 1.0f / (1.0f + expf(-(p1 + b2v)));
        }
    }
}

// ============ Kernel B: patch scores + stable top-768 ============
__global__ __launch_bounds__(1024) void select_kernel()
{
    const int b = blockIdx.x;
    const int p = threadIdx.x;
    __shared__ float s[NP];
    __shared__ int   woff[32];

    const int pr = p >> 5, pc = p & 31;
    const float* base = g_imp + b * NTOK;
    float sum = 0.0f;
#pragma unroll
    for (int i = 0; i < 4; i++) {
        float4 v = *(const float4*)(base + (pr * 4 + i) * WW + pc * 4);
        sum += (v.x + v.y) + (v.z + v.w);
    }
    s[p] = sum;                          // sum monotone in mean; ranking identical
    __syncthreads();

    const float sp = sum;
    int rank = 0;
    const float4* s4 = (const float4*)s;
#pragma unroll 4
    for (int j4 = 0; j4 < NP / 4; j4++) {
        float4 v = s4[j4];
        int j = j4 * 4;
        rank += (int)((v.x > sp) || (v.x == sp && (j + 0) < p));
        rank += (int)((v.y > sp) || (v.y == sp && (j + 1) < p));
        rank += (int)((v.z > sp) || (v.z == sp && (j + 2) < p));
        rank += (int)((v.w > sp) || (v.w == sp && (j + 3) < p));
    }
    const bool kept = (rank < KKEEP);

    const unsigned mask = __ballot_sync(0xffffffffu, kept);
    const int lane = p & 31, warp = p >> 5;
    const int lpre = __popc(mask & ((1u << lane) - 1u));
    if (lane == 0) woff[warp] = __popc(mask);
    __syncthreads();
    if (p < 32) {
        int v = woff[p];
        int inc = v;
        for (int d = 1; d < 32; d <<= 1) {
            int t = __shfl_up_sync(0xffffffffu, inc, d);
            if (lane >= d) inc += t;
        }
        woff[p] = inc - v;
    }
    __syncthreads();
    if (kept)
        g_idx[b * KKEEP + woff[warp] + lpre] = p;
}

// ============ Kernel C: gather + spatial reassembly ============
__global__ __launch_bounds__(128) void gather_kernel(
    const float* __restrict__ tokens, float* __restrict__ out)
{
    const int k = blockIdx.x;
    const int b = blockIdx.y;
    const int p = g_idx[b * KKEEP + k];
    const int pr = p >> 5, pc = p & 31;
    const int kr = k >> 5, kc = k & 31;

    const float4* src = (const float4*)(tokens + (size_t)b * NTOK * CC);
    float4*       dst = (float4*)(out + (size_t)b * (KKEEP * 16) * CC);
    const int t = threadIdx.x;

#pragma unroll
    for (int i = 0; i < 4; i++) {
        size_t so   = (size_t)((pr * 4 + i) * WW + pc * 4) * (CC / 4);
        size_t dofs = (size_t)((kr * 4 + i) * WW + kc * 4) * (CC / 4);
#pragma unroll
        for (int it = 0; it < 2; it++) {
            int e = it * 128 + t;
            dst[dofs + e] = src[so + e];
        }
    }
}

// ============================ launch ============================
extern "C" void kernel_launch(void* const* d_in, const int* in_sizes, int n_in,
                              void* d_out, int out_size)
{
    const float* tokens = (const float*)d_in[0];
    const float* w1 = (const float*)d_in[1];
    const float* b1 = (const float*)d_in[2];
    const float* w2 = (const float*)d_in[3];
    const float* b2 = (const float*)d_in[4];
    (void)in_sizes; (void)n_in; (void)out_size;

    cudaFuncSetAttribute(score_mma, cudaFuncAttributeMaxDynamicSharedMemorySize, SMEM_SZ);
    score_mma<<<NBLK, 256, SMEM_SZ>>>(tokens, w1, b1, w2, b2);
    select_kernel<<<BATCH, 1024>>>();
    gather_kernel<<<dim3(KKEEP, BATCH), 128>>>(tokens, (float*)d_out);
}